// round 16
// baseline (speedup 1.0000x reference)
#include <cuda_runtime.h>
#include <cuda_fp16.h>

// Problem constants (fixed dataset shapes)
#define B     8192
#define D     128
#define DG    64        // gathered dim (Da = Dv = 64)
#define TM    64        // query rows per CTA
#define NCTA  (B / TM)  // 128 x 2 pairs = 256 lse CTAs
#define SROWH 72        // padded halves per smem row (144B; conflict-free frags)
#define L2E   1.4426950408889634f

typedef unsigned int u32;

// fp16 gathered matrices, row-major [row][DG].
// K matrices pre-scaled by log2(e) so the epilogue is a bare exp2.
// 0=Q0(V1: v@ia) 1=K0'(A1*L2E) 2=Q1(A2: a@ii) 3=K1'(V2*L2E)
__device__ __half g_h[4][(size_t)B * DG];

// plain per-CTA partials; combined by a dedicated finalize kernel (race-free)
__device__ float g_diagp[256];
__device__ float g_lsep[2 * NCTA];

// ---------------------------------------------------------------------------
// helpers
// ---------------------------------------------------------------------------
__device__ __forceinline__ float ex2a(float x) {
    float y;
    asm("ex2.approx.f32 %0, %1;" : "=f"(y) : "f"(x));
    return y;
}

// m16n8k16 fp16 MMA, fp32 accumulate (baseline PTX — compiles for compute_103)
__device__ __forceinline__ void hmma(float c[4], const u32 a[4], u32 b0, u32 b1) {
    asm("mma.sync.aligned.m16n8k16.row.col.f32.f16.f16.f32 "
        "{%0,%1,%2,%3}, {%4,%5,%6,%7}, {%8,%9}, {%0,%1,%2,%3};"
        : "+f"(c[0]), "+f"(c[1]), "+f"(c[2]), "+f"(c[3])
        : "r"(a[0]), "r"(a[1]), "r"(a[2]), "r"(a[3]), "r"(b0), "r"(b1));
}

// ---------------------------------------------------------------------------
// index dtype detection (harness delivers the int64 arrays as int32 —
// verified round 7; detection kept for robustness)
// ---------------------------------------------------------------------------
__device__ __forceinline__ int detect_i64(const void* p) {
    const long long* q = (const long long*)p;
    #pragma unroll
    for (int i = 0; i < 32; i++) {
        long long v = q[i];
        if (v < 0 || v >= D) return 0;
    }
    return 1;
}
__device__ __forceinline__ int idx_at(const void* p, int c, int is64) {
    return is64 ? (int)((const long long*)p)[c] : ((const int*)p)[c];
}

// ---------------------------------------------------------------------------
// fused gather: EXACT Round-12 scalar-store body (the passing version),
// only the output of the diag partial changed (plain store, no atomic).
// 32 rows/block, 256 threads.
// ---------------------------------------------------------------------------
__global__ void convert_diag(const float* __restrict__ a, const float* __restrict__ v,
                             const void* __restrict__ ia, const void* __restrict__ ii) {
    __shared__ int ja_s[DG], ji_s[DG];
    __shared__ int mode_sh;
    int tid = threadIdx.x;
    if (tid == 0) mode_sh = detect_i64(ia) & detect_i64(ii);
    __syncthreads();
    if (tid < DG) {
        ja_s[tid] = idx_at(ia, tid, mode_sh);
        ji_s[tid] = idx_at(ii, tid, mode_sh);
    }
    __syncthreads();

    int row = blockIdx.x * 32 + (tid >> 3);
    int c0  = (tid & 7) * 8;
    const float* ar = a + (size_t)row * D;
    const float* vr = v + (size_t)row * D;
    float p = 0.0f;
    #pragma unroll
    for (int cc = 0; cc < 8; cc++) {
        int c  = c0 + cc;
        int ja = ja_s[c], ji = ji_s[c];
        float va = vr[ja], aa = ar[ja];      // Q0, K0 source
        float ai = ar[ji], vi = vr[ji];      // Q1, K1 source
        g_h[0][(size_t)row * DG + c] = __float2half(va);
        g_h[1][(size_t)row * DG + c] = __float2half(aa * L2E);
        g_h[2][(size_t)row * DG + c] = __float2half(ai);
        g_h[3][(size_t)row * DG + c] = __float2half(vi * L2E);
        p += va * aa + ai * vi;              // exact diag contribution
    }
    #pragma unroll
    for (int o = 16; o; o >>= 1) p += __shfl_down_sync(0xffffffffu, p, o);
    __shared__ float w[8];
    if ((tid & 31) == 0) w[tid >> 5] = p;
    __syncthreads();
    if (tid == 0) {
        float s = 0.0f;
        #pragma unroll
        for (int i = 0; i < 8; i++) s += w[i];
        g_diagp[blockIdx.x] = s;
    }
}

// ---------------------------------------------------------------------------
// main: fp16 mma.sync QK'^T + all-MUFU ex2 epilogue (Round-12 exact form)
// + lse reduce -> per-CTA partial.
// grid (128, 2) = 256 CTAs, 2 CTAs/SM. 8 warps: 2(M) x 4(N) over 64x128.
// ---------------------------------------------------------------------------
__global__ __launch_bounds__(256, 2)
void lse_kernel() {
    __shared__ __half sQ[TM * SROWH];
    __shared__ __half sK[128 * SROWH];
    __shared__ float  red[TM * 4];
    __shared__ float  wsum[8];

    const int tid    = threadIdx.x;
    const int lane   = tid & 31;
    const int wid    = tid >> 5;
    const int g      = lane >> 2;      // 0..7  (fragment row group)
    const int t4     = lane & 3;       // 0..3  (fragment col pair)
    const int warp_m = wid & 1;        // 0..1 -> 32 M-rows each
    const int warp_n = wid >> 1;       // 0..3 -> 32 N-cols each

    const int pair  = blockIdx.y;
    const int qBase = blockIdx.x * TM;
    const __half* Qg = g_h[2 * pair];
    const __half* Kg = g_h[2 * pair + 1];

    // ---- load Q tile to smem (padded), then A fragments into registers ----
    for (int i = tid; i < TM * 8; i += 256) {
        int r = i >> 3, c = i & 7;
        *(uint4*)&sQ[r * SROWH + c * 8] =
            *(const uint4*)&Qg[(size_t)(qBase + r) * DG + c * 8];
    }
    __syncthreads();

    u32 aF[2][4][4];                   // [m16-frag][kstep][reg]
    #pragma unroll
    for (int f = 0; f < 2; f++) {
        int r0 = warp_m * 32 + f * 16 + g;
        #pragma unroll
        for (int ks = 0; ks < 4; ks++) {
            int cb = ks * 16 + 2 * t4;
            aF[f][ks][0] = *(const u32*)&sQ[r0 * SROWH + cb];
            aF[f][ks][1] = *(const u32*)&sQ[(r0 + 8) * SROWH + cb];
            aF[f][ks][2] = *(const u32*)&sQ[r0 * SROWH + cb + 8];
            aF[f][ks][3] = *(const u32*)&sQ[(r0 + 8) * SROWH + cb + 8];
        }
    }

    float rsum[4] = {0.f, 0.f, 0.f, 0.f};

    // ---- prime prefetch of K tile 0 (128 keys x 64 dims = 1024 uint4) ----
    uint4 pf[4];
    #pragma unroll
    for (int j = 0; j < 4; j++) {
        int idx = tid + j * 256, r = idx >> 3, c = idx & 7;
        pf[j] = *(const uint4*)&Kg[(size_t)r * DG + c * 8];
    }

    for (int t = 0; t < B / 128; t++) {
        #pragma unroll
        for (int j = 0; j < 4; j++) {
            int idx = tid + j * 256, r = idx >> 3, c = idx & 7;
            *(uint4*)&sK[r * SROWH + c * 8] = pf[j];
        }
        __syncthreads();

        if (t < B / 128 - 1) {
            #pragma unroll
            for (int j = 0; j < 4; j++) {
                int idx = tid + j * 256, r = idx >> 3, c = idx & 7;
                pf[j] = *(const uint4*)&Kg[(size_t)((t + 1) * 128 + r) * DG + c * 8];
            }
        }

        float cf[2][4][4];
        #pragma unroll
        for (int f = 0; f < 2; f++)
            #pragma unroll
            for (int nb = 0; nb < 4; nb++)
                #pragma unroll
                for (int k = 0; k < 4; k++) cf[f][nb][k] = 0.0f;

        #pragma unroll
        for (int ks = 0; ks < 4; ks++) {
            #pragma unroll
            for (int nb = 0; nb < 4; nb++) {
                int nr = warp_n * 32 + nb * 8 + g;
                int cb = ks * 16 + 2 * t4;
                u32 b0 = *(const u32*)&sK[nr * SROWH + cb];
                u32 b1 = *(const u32*)&sK[nr * SROWH + cb + 8];
                hmma(cf[0][nb], aF[0][ks], b0, b1);
                hmma(cf[1][nb], aF[1][ks], b0, b1);
            }
        }
        __syncthreads();               // all reads of sK done

        // epilogue: Round-12 exact form — all values through MUFU ex2
        #pragma unroll
        for (int f = 0; f < 2; f++) {
            float s0 = 0.f, s1 = 0.f;
            #pragma unroll
            for (int nb = 0; nb < 4; nb++) {
                s0 += ex2a(cf[f][nb][0]) + ex2a(cf[f][nb][1]);
                s1 += ex2a(cf[f][nb][2]) + ex2a(cf[f][nb][3]);
            }
            rsum[f * 2 + 0] += s0;     // row g
            rsum[f * 2 + 1] += s1;     // row g+8
        }
    }

    // ---- reduce: quad lanes (cols), then 4 warp_n strips, then log ----
    #pragma unroll
    for (int i = 0; i < 4; i++) {
        rsum[i] += __shfl_xor_sync(0xffffffffu, rsum[i], 1);
        rsum[i] += __shfl_xor_sync(0xffffffffu, rsum[i], 2);
    }
    if (t4 == 0) {
        #pragma unroll
        for (int f = 0; f < 2; f++)
            #pragma unroll
            for (int h = 0; h < 2; h++) {
                int row = warp_m * 32 + f * 16 + h * 8 + g;
                red[row * 4 + warp_n] = rsum[f * 2 + h];
            }
    }
    __syncthreads();

    float part = 0.0f;
    if (tid < TM)
        part = logf(red[tid * 4] + red[tid * 4 + 1] +
                    red[tid * 4 + 2] + red[tid * 4 + 3]);
    #pragma unroll
    for (int o = 16; o; o >>= 1) part += __shfl_down_sync(0xffffffffu, part, o);
    if (lane == 0) wsum[wid] = part;
    __syncthreads();

    if (tid == 0) {
        float s = 0.0f;
        #pragma unroll
        for (int i = 0; i < 8; i++) s += wsum[i];
        g_lsep[blockIdx.x + blockIdx.y * gridDim.x] = s;   // plain store
    }
}

// ---------------------------------------------------------------------------
// finalize: one CTA combines all partials and writes the scalar output.
// Race-free (kernel-boundary ordering only), deterministic across replays.
// ---------------------------------------------------------------------------
__global__ void finalize(float* __restrict__ out) {
    int tid = threadIdx.x;
    float s = g_lsep[tid] - g_diagp[tid];
    #pragma unroll
    for (int o = 16; o; o >>= 1) s += __shfl_down_sync(0xffffffffu, s, o);
    __shared__ float w[8];
    if ((tid & 31) == 0) w[tid >> 5] = s;
    __syncthreads();
    if (tid == 0) {
        float tot = 0.0f;
        #pragma unroll
        for (int i = 0; i < 8; i++) tot += w[i];
        out[0] = tot * (1.0f / (float)B);
    }
}

// ---------------------------------------------------------------------------
// Size-based input binding (robust to metadata ordering):
//   two 1048576-element float buffers  -> a_features, then v_features
//   two 64-element index buffers       -> audio_only, then image_only
// ---------------------------------------------------------------------------
extern "C" void kernel_launch(void* const* d_in, const int* in_sizes, int n_in,
                              void* d_out, int out_size) {
    const float* a  = 0;
    const float* v  = 0;
    const void*  ia = 0;
    const void*  ii = 0;
    for (int i = 0; i < n_in; i++) {
        if (in_sizes[i] == B * D) {
            if (!a) a = (const float*)d_in[i];
            else if (!v) v = (const float*)d_in[i];
        } else if (in_sizes[i] == DG) {
            if (!ia) ia = d_in[i];
            else if (!ii) ii = d_in[i];
        }
    }
    float* out = (float*)d_out;

    convert_diag<<<B / 32, 256>>>(a, v, ia, ii);
    lse_kernel<<<dim3(B / TM, 2), 256>>>();
    finalize<<<1, 256>>>(out);
}